// round 2
// baseline (speedup 1.0000x reference)
#include <cuda_runtime.h>
#include <cuda_bf16.h>
#include <cstdint>

// Problem constants
#define BS      32
#define SEQ_LEN 4096
#define HIDDEN  1024

__device__ __forceinline__ unsigned rotl32(unsigned x, int r) {
    return (x << r) | (x >> (32 - r));
}

// One block per batch row. 1024 threads: thread t owns emb index t.
__global__ void __launch_bounds__(1024, 1)
condensed_embracement_kernel(const float* __restrict__ tokens,
                             const int*   __restrict__ mask,
                             float*       __restrict__ out) {
    const int b = blockIdx.x;
    const int t = threadIdx.x;

    // ---- Phase 1: prefix length = sum of mask row (mask is 1^L 0^(S-L)) ----
    const int4* m4 = reinterpret_cast<const int4*>(mask + (size_t)b * SEQ_LEN);
    int4 mv = m4[t];
    int s = mv.x + mv.y + mv.z + mv.w;

    #pragma unroll
    for (int o = 16; o > 0; o >>= 1)
        s += __shfl_down_sync(0xffffffffu, s, o);

    __shared__ int wsum[32];
    __shared__ int prefix_sh;
    if ((t & 31) == 0) wsum[t >> 5] = s;
    __syncthreads();
    if (t < 32) {
        int x = wsum[t];
        #pragma unroll
        for (int o = 16; o > 0; o >>= 1)
            x += __shfl_down_sync(0xffffffffu, x, o);
        if (t == 0) prefix_sh = x;
    }
    __syncthreads();

    const int prefix  = prefix_sh;
    const int n_valid = max(prefix - 1, 1);

    // ---- Phase 2: jax.random.uniform(jax.random.key(42), (32,1024)) ----
    // PARTITIONABLE threefry (JAX default): element j gets 64-bit counter j.
    // Lanes: x0 = hi32(j) = 0, x1 = lo32(j) = j. Key = (0, 42).
    // 32-bit output = out0 ^ out1.
    const unsigned j = (unsigned)(b * HIDDEN + t);

    const unsigned k0 = 0u;
    const unsigned k1 = 42u;
    const unsigned k2 = k0 ^ k1 ^ 0x1BD11BDAu;

    unsigned x0 = 0u + k0;   // counts_hi + ks[0]
    unsigned x1 = j  + k1;   // counts_lo + ks[1]

    #define TF_ROUND(r) { x0 += x1; x1 = rotl32(x1, (r)); x1 ^= x0; }
    TF_ROUND(13) TF_ROUND(15) TF_ROUND(26) TF_ROUND(6)
    x0 += k1; x1 += k2 + 1u;
    TF_ROUND(17) TF_ROUND(29) TF_ROUND(16) TF_ROUND(24)
    x0 += k2; x1 += k0 + 2u;
    TF_ROUND(13) TF_ROUND(15) TF_ROUND(26) TF_ROUND(6)
    x0 += k0; x1 += k1 + 3u;
    TF_ROUND(17) TF_ROUND(29) TF_ROUND(16) TF_ROUND(24)
    x0 += k1; x1 += k2 + 4u;
    TF_ROUND(13) TF_ROUND(15) TF_ROUND(26) TF_ROUND(6)
    x0 += k2; x1 += k0 + 5u;
    #undef TF_ROUND

    const unsigned bits = x0 ^ x1;

    // uniform in [0,1): bitcast((bits>>9) | 0x3f800000) - 1.0f, exactly like JAX
    const float u = __fsub_rn(__uint_as_float((bits >> 9) | 0x3f800000u), 1.0f);

    // idx = min(int(u * n_valid), n_valid - 1); f32 mul RN, truncating convert
    int idx = (int)__fmul_rn(u, (float)n_valid);
    idx = min(idx, n_valid - 1);

    // ---- Phase 3: gather ----
    out[(size_t)b * HIDDEN + t] =
        tokens[(size_t)b * SEQ_LEN * HIDDEN + (size_t)idx * HIDDEN + t];
}

extern "C" void kernel_launch(void* const* d_in, const int* in_sizes, int n_in,
                              void* d_out, int out_size) {
    // Defensive input dispatch by element count (tokens = 32*4096*1024).
    const float* tokens;
    const int*   mask;
    if (in_sizes[0] == BS * SEQ_LEN * HIDDEN) {
        tokens = (const float*)d_in[0];
        mask   = (const int*)d_in[1];
    } else {
        tokens = (const float*)d_in[1];
        mask   = (const int*)d_in[0];
    }
    float* out = (float*)d_out;   // (32, 1024) fp32
    (void)n_in; (void)out_size;

    condensed_embracement_kernel<<<BS, 1024>>>(tokens, mask, out);
}